// round 16
// baseline (speedup 1.0000x reference)
#include <cuda_runtime.h>

#define NPTS  4096
#define NCTA  128
#define TPB   512
#define IPC   32          // i-points per CTA
#define NSL   64          // j-slices (strided pairs)
#define STEPS 10
#define NSIT  6           // Newton-Schulz iterations
#define NCNT  8           // arrival counters (16 CTAs each)
#define GPC   (NCTA/NCNT) // 16
#define CONV_THRESH 8     // stop when <= this many matches changed (of 4096)
#define F_APPLYSTOP 64    // flag bit: apply published R, then stop
#define F_STOP      128   // flag bit: stop without applying (R=I case)

// shared memory layout (bytes) — SoA p2: qx,qy,qz,qw (16KB each)
#define SM_QX    0
#define SM_QY    (NPTS*4)
#define SM_QZ    (NPTS*8)
#define SM_QW    (NPTS*12)
#define SM_KEY   (NPTS*16)               // u64[NSL][32]  = 16384
#define SM_MYPC  (SM_KEY + NSL*32*8)     // float[96]
#define SM_MYP1  (SM_MYPC + 96*4)        // float[96]
#define SM_SRT   (SM_MYP1 + 96*4)        // float[12] (+pad)
#define SM_SRED  (SM_SRT + 16*4)         // float[4][15] (+pad)
#define SM_PREV  (SM_SRED + 64*4)        // int[32]
#define SM_CHG   (SM_PREV + 32*4)        // int[8]
#define SM_FLG   (SM_CHG + 8*4)          // int[4]
#define SM_TOTAL (SM_FLG + 16 + 64)

// global scratch (no allocations allowed)
__device__ float g_part[NCTA][16];
__device__ int   g_cnt[NCNT][32];   // word0: arrivals (monotone), word1: changed (monotone)
__device__ float g_rel[NCNT][32];   // per-group release line: [0..11]=R,t  int@[13]=flag

__device__ __forceinline__ unsigned int fkey(float f) {
    unsigned int u = __float_as_uint(f);
    return (u & 0x80000000u) ? ~u : (u | 0x80000000u);
}

__device__ __forceinline__ void arrive_release(int* ctr) {
    asm volatile("red.release.gpu.global.add.u32 [%0], 1;" :: "l"(ctr) : "memory");
}
__device__ __forceinline__ void add_relaxed(int* ctr) {
    asm volatile("red.relaxed.gpu.global.add.u32 [%0], 1;" :: "l"(ctr) : "memory");
}
__device__ __forceinline__ int ld_acquire(const int* p) {
    int v;
    asm volatile("ld.acquire.gpu.global.u32 %0, [%1];" : "=r"(v) : "l"(p) : "memory");
    return v;
}
__device__ __forceinline__ void st_release(int* p, int v) {
    asm volatile("st.release.gpu.global.u32 [%0], %1;" :: "l"(p), "r"(v) : "memory");
}

// packed f32x2 helpers (FFMA2 path — per-lane arithmetic identical to fmaf)
__device__ __forceinline__ unsigned long long pack2(float lo, float hi) {
    unsigned long long r;
    asm("mov.b64 %0, {%1, %2};" : "=l"(r) : "f"(lo), "f"(hi));
    return r;
}
__device__ __forceinline__ void unpack2(unsigned long long v, float& lo, float& hi) {
    asm("mov.b64 {%0, %1}, %2;" : "=f"(lo), "=f"(hi) : "l"(v));
}
__device__ __forceinline__ unsigned long long fma2(unsigned long long a,
                                                   unsigned long long b,
                                                   unsigned long long c) {
    unsigned long long d;
    asm("fma.rn.f32x2 %0, %1, %2, %3;" : "=l"(d) : "l"(a), "l"(b), "l"(c));
    return d;
}

// ---------------------------------------------------------------------------
// Newton-Schulz polar: Q = orthogonal polar factor of M (3x3, det(M)>0).
// ---------------------------------------------------------------------------
__device__ __forceinline__ void polar3(const float M[9], float Q[9])
{
    float f2 = 0.f;
    #pragma unroll
    for (int q = 0; q < 9; q++) f2 = fmaf(M[q], M[q], f2);
    float inv = rsqrtf(f2);
    float X[9];
    #pragma unroll
    for (int q = 0; q < 9; q++) X[q] = M[q]*inv;

    #pragma unroll
    for (int it = 0; it < NSIT; it++) {
        float W[9];
        #pragma unroll
        for (int i = 0; i < 3; i++)
            #pragma unroll
            for (int j = 0; j < 3; j++)
                W[3*i+j] = fmaf(X[0+i], X[0+j],
                           fmaf(X[3+i], X[3+j], X[6+i]*X[6+j]));
        float Y[9];
        #pragma unroll
        for (int i = 0; i < 3; i++)
            #pragma unroll
            for (int j = 0; j < 3; j++)
                Y[3*i+j] = fmaf(X[3*i+0], W[0+j],
                           fmaf(X[3*i+1], W[3+j], X[3*i+2]*W[6+j]));
        #pragma unroll
        for (int q = 0; q < 9; q++) X[q] = fmaf(1.5f, X[q], -0.5f*Y[q]);
    }
    #pragma unroll
    for (int q = 0; q < 9; q++) Q[q] = X[q];
}

// warp-reduce 15 accumulators (full warp, fixed order -> deterministic)
__device__ __forceinline__ void wred15(float a[15]) {
    #pragma unroll
    for (int q = 0; q < 15; q++)
        #pragma unroll
        for (int off = 16; off; off >>= 1)
            a[q] += __shfl_down_sync(0xffffffffu, a[q], off);
}

// solve from reduced sums (sred[4][15] in smem) -> R[9], t[3]
__device__ __forceinline__ void solve_from_sred(const float* sred,
                                                float R[9], float t[3])
{
    float s15[15];
    #pragma unroll
    for (int q = 0; q < 15; q++)
        s15[q] = (sred[q] + sred[15+q]) + (sred[30+q] + sred[45+q]);
    const float invN = 1.0f/NPTS;
    float c1[3] = { s15[0]*invN, s15[1]*invN, s15[2]*invN };
    float c2[3] = { s15[3]*invN, s15[4]*invN, s15[5]*invN };
    float M[9];
    #pragma unroll
    for (int i = 0; i < 3; i++)
        #pragma unroll
        for (int j = 0; j < 3; j++)
            M[3*i+j] = s15[6+3*j+i] - (float)NPTS * c1[j] * c2[i];
    polar3(M, R);
    t[0] = c2[0] - (R[0]*c1[0] + R[1]*c1[1] + R[2]*c1[2]);
    t[1] = c2[1] - (R[3]*c1[0] + R[4]*c1[1] + R[5]*c1[2]);
    t[2] = c2[2] - (R[6]*c1[0] + R[7]*c1[1] + R[8]*c1[2]);
}

// ---------------------------------------------------------------------------
// Persistent kernel: R15 NN + thresholded convergence stop + replicated
// per-group release lines (R,t + flag on one 128B line per 16 CTAs).
// ---------------------------------------------------------------------------
__global__ void __launch_bounds__(TPB, 1)
icp_all(const float* __restrict__ p1, const float* __restrict__ p2,
        float* __restrict__ out)
{
    extern __shared__ unsigned char smem[];
    float*              qxs  = (float*)(smem + SM_QX);
    float*              qys  = (float*)(smem + SM_QY);
    float*              qzs  = (float*)(smem + SM_QZ);
    float*              qws  = (float*)(smem + SM_QW);
    unsigned long long* key  = (unsigned long long*)(smem + SM_KEY);
    float*              mypc = (float*)(smem + SM_MYPC);
    float*              myp1 = (float*)(smem + SM_MYP1);
    float*              srt  = (float*)(smem + SM_SRT);
    float*              sred = (float*)(smem + SM_SRED);
    int*                previdx = (int*)(smem + SM_PREV);
    int*                schg = (int*)(smem + SM_CHG);
    int*                sflg = (int*)(smem + SM_FLG);

    const int cta = blockIdx.x;
    const int tid = threadIdx.x;
    const int grp = cta & (NCNT-1);

    // SoA p2 (+ precomputed 0.5|q|^2); reused all iterations
    for (int j = tid; j < NPTS; j += TPB) {
        float a = p2[j*3+0], b = p2[j*3+1], c = p2[j*3+2];
        qxs[j] = a; qys[j] = b; qzs[j] = c;
        qws[j] = 0.5f*fmaf(a,a,fmaf(b,b,c*c));
    }
    if (tid < IPC) {
        int i = cta*IPC + tid;
        float x = p1[i*3+0], y = p1[i*3+1], z = p1[i*3+2];
        myp1[tid*3+0] = x; myp1[tid*3+1] = y; myp1[tid*3+2] = z;
        mypc[tid*3+0] = x; mypc[tid*3+1] = y; mypc[tid*3+2] = z;
        previdx[tid] = -1;
    }
    __syncthreads();

    const int iblk  = tid & 7;        // 8 i-blocks of 4 points
    const int slice = tid >> 3;       // 64 slices, strided j-pairs
    const int ib4   = iblk*4;

    int arrived = 0;
    int prevChangedTotal = 0;
    int fval = 0;

    for (int k = 0; k < STEPS; k++) {
        // --- NN: 4 i-points, 32 strided j-pairs per thread, FFMA2 packed ---
        {
            float x0=mypc[(ib4+0)*3+0], y0=mypc[(ib4+0)*3+1], z0=mypc[(ib4+0)*3+2];
            float x1=mypc[(ib4+1)*3+0], y1=mypc[(ib4+1)*3+1], z1=mypc[(ib4+1)*3+2];
            float x2=mypc[(ib4+2)*3+0], y2=mypc[(ib4+2)*3+1], z2=mypc[(ib4+2)*3+2];
            float x3=mypc[(ib4+3)*3+0], y3=mypc[(ib4+3)*3+1], z3=mypc[(ib4+3)*3+2];

            const unsigned long long nx0 = pack2(-x0,-x0), ny0 = pack2(-y0,-y0), nz0 = pack2(-z0,-z0);
            const unsigned long long nx1 = pack2(-x1,-x1), ny1 = pack2(-y1,-y1), nz1 = pack2(-z1,-z1);
            const unsigned long long nx2 = pack2(-x2,-x2), ny2 = pack2(-y2,-y2), nz2 = pack2(-z2,-z2);
            const unsigned long long nx3 = pack2(-x3,-x3), ny3 = pack2(-y3,-y3), nz3 = pack2(-z3,-z3);

            float b0=3.4028235e38f, b1=b0, b2=b0, b3=b0;
            int   j0=0, j1=0, j2=0, j3=0;
            int jb = slice*2;                // pairs {jb, jb+1}, stride 128
            #pragma unroll 8
            for (int m = 0; m < 32; m++, jb += 128) {
                unsigned long long QX = *(const unsigned long long*)(qxs + jb);
                unsigned long long QY = *(const unsigned long long*)(qys + jb);
                unsigned long long QZ = *(const unsigned long long*)(qzs + jb);
                unsigned long long QW = *(const unsigned long long*)(qws + jb);
                float sa, sb;
                unpack2(fma2(nx0, QX, fma2(ny0, QY, fma2(nz0, QZ, QW))), sa, sb);
                if (sa < b0) { b0 = sa; j0 = jb; }       // ascending j: first-index ties
                if (sb < b0) { b0 = sb; j0 = jb+1; }
                unpack2(fma2(nx1, QX, fma2(ny1, QY, fma2(nz1, QZ, QW))), sa, sb);
                if (sa < b1) { b1 = sa; j1 = jb; }
                if (sb < b1) { b1 = sb; j1 = jb+1; }
                unpack2(fma2(nx2, QX, fma2(ny2, QY, fma2(nz2, QZ, QW))), sa, sb);
                if (sa < b2) { b2 = sa; j2 = jb; }
                if (sb < b2) { b2 = sb; j2 = jb+1; }
                unpack2(fma2(nx3, QX, fma2(ny3, QY, fma2(nz3, QZ, QW))), sa, sb);
                if (sa < b3) { b3 = sa; j3 = jb; }
                if (sb < b3) { b3 = sb; j3 = jb+1; }
            }
            key[slice*32 + ib4+0] = ((unsigned long long)fkey(b0) << 32) | (unsigned)j0;
            key[slice*32 + ib4+1] = ((unsigned long long)fkey(b1) << 32) | (unsigned)j1;
            key[slice*32 + ib4+2] = ((unsigned long long)fkey(b2) << 32) | (unsigned)j2;
            key[slice*32 + ib4+3] = ((unsigned long long)fkey(b3) << 32) | (unsigned)j3;
        }
        __syncthreads();

        // --- parallel key-reduce: 64 slices -> 8 (256 threads) ---
        if (tid < 256) {
            const int pt  = tid & 31;
            const int oct = tid >> 5;
            unsigned long long best = key[(oct*8)*32 + pt];
            #pragma unroll
            for (int s2 = 1; s2 < 8; s2++) {
                unsigned long long v = key[(oct*8+s2)*32 + pt];
                if (v < best) best = v;
            }
            key[oct*32 + pt] = best;
        }
        __syncthreads();

        // --- warp0: final argmin + changed + partials + arrive ---
        if (tid < 32) {
            unsigned long long best = key[tid];
            #pragma unroll
            for (int s2 = 1; s2 < 8; s2++) {
                unsigned long long v = key[s2*32 + tid];
                if (v < best) best = v;   // (score, j) lexicographic: first-index ties
            }
            const int idx = (int)(unsigned)(best & 0xFFFFFFFFu);
            int changed = (idx != previdx[tid]);
            previdx[tid] = idx;
            unsigned cm = __ballot_sync(0xffffffffu, changed);
            int nch = __popc(cm);

            float dx = qxs[idx], dy = qys[idx], dz = qzs[idx];
            float sx = mypc[tid*3+0], sy = mypc[tid*3+1], sz = mypc[tid*3+2];
            float a[15];
            a[0]=sx; a[1]=sy; a[2]=sz; a[3]=dx; a[4]=dy; a[5]=dz;
            a[6]=sx*dx; a[7]=sx*dy; a[8]=sx*dz;
            a[9]=sy*dx; a[10]=sy*dy; a[11]=sy*dz;
            a[12]=sz*dx; a[13]=sz*dy; a[14]=sz*dz;
            wred15(a);
            if (tid == 0) {
                volatile float* gp = g_part[cta];
                #pragma unroll
                for (int q2 = 0; q2 < 15; q2++) gp[q2] = a[q2];
                // per-point changed count (exact): add nch, not 1
                for (int c2 = 0; c2 < nch; c2++) { }  // (count folded below)
                if (nch) {
                    asm volatile("red.relaxed.gpu.global.add.u32 [%0], %1;"
                                 :: "l"(&g_cnt[grp][1]), "r"((unsigned)nch) : "memory");
                }
                arrive_release(&g_cnt[grp][0]);       // orders partials + changed
            }
        }
        arrived++;

        if (cta == 0) {
            if (tid < NCNT) {
                const int target = GPC * arrived;
                while (ld_acquire(&g_cnt[tid][0]) < target) { }
                schg[tid] = *(volatile int*)&g_cnt[tid][1];
            }
            __syncthreads();
            {
                float a[15];
                if (tid < NCTA) {
                    volatile float* gp = g_part[tid];
                    #pragma unroll
                    for (int q = 0; q < 15; q++) a[q] = gp[q];
                    wred15(a);
                    if ((tid & 31) == 0) {
                        #pragma unroll
                        for (int q = 0; q < 15; q++) sred[(tid>>5)*15 + q] = a[q];
                    }
                }
            }
            __syncthreads();
            if (tid == 0) {
                int total = ((schg[0]+schg[1])+(schg[2]+schg[3]))
                          + ((schg[4]+schg[5])+(schg[6]+schg[7]));
                int newly = total - prevChangedTotal;
                prevChangedTotal = total;
                int f;
                if (newly == 0) {
                    f = (k+1) | F_STOP;         // matches frozen: R=I exactly, skip
                } else {
                    float R[9], t[3];
                    solve_from_sred(sred, R, t);
                    #pragma unroll
                    for (int q = 0; q < 9; q++) srt[q] = R[q];
                    srt[9]=t[0]; srt[10]=t[1]; srt[11]=t[2];
                    f = (k+1) | ((newly <= CONV_THRESH) ? F_APPLYSTOP : 0);
                }
                sflg[0] = f;
            }
            __syncthreads();
            fval = sflg[0];
            // replicate release line (R,t + flag) to 8 lines, one per group
            if (tid < NCNT) {
                float* line = g_rel[tid];
                if (!(fval & F_STOP)) {
                    #pragma unroll
                    for (int q = 0; q < 12; q++)
                        ((volatile float*)line)[q] = srt[q];
                }
                st_release(&((int*)line)[13], fval);   // same-thread order: data->flag
            }
        } else {
            // workers: poll own group's release line, read R,t from same line
            if (tid < 16) {
                const int* fp = &((const int*)g_rel[grp])[13];
                int f;
                while (((f = ld_acquire(fp)) & 63) < k + 1) { }
                if (tid == 12) sflg[0] = f;
                if (tid < 12) srt[tid] = ((volatile float*)g_rel[grp])[tid];
            }
            __syncthreads();
            fval = sflg[0];
        }

        // --- apply R_k, t_k (unless STOP) ---
        if (!(fval & F_STOP) && tid < IPC) {
            float x = mypc[tid*3+0], y = mypc[tid*3+1], z = mypc[tid*3+2];
            float nx = fmaf(srt[0],x, fmaf(srt[1],y, fmaf(srt[2],z, srt[9])));
            float ny = fmaf(srt[3],x, fmaf(srt[4],y, fmaf(srt[5],z, srt[10])));
            float nz = fmaf(srt[6],x, fmaf(srt[7],y, fmaf(srt[8],z, srt[11])));
            mypc[tid*3+0] = nx; mypc[tid*3+1] = ny; mypc[tid*3+2] = nz;
        }
        __syncthreads();
        if (fval & (F_STOP | F_APPLYSTOP)) break;
    }

    // --- final solve: Kabsch(p1 -> pc_final) ---
    if (tid < 32) {
        float sx = myp1[tid*3+0], sy = myp1[tid*3+1], sz = myp1[tid*3+2];
        float dx = mypc[tid*3+0], dy = mypc[tid*3+1], dz = mypc[tid*3+2];
        float a[15];
        a[0]=sx; a[1]=sy; a[2]=sz; a[3]=dx; a[4]=dy; a[5]=dz;
        a[6]=sx*dx; a[7]=sx*dy; a[8]=sx*dz;
        a[9]=sy*dx; a[10]=sy*dy; a[11]=sy*dz;
        a[12]=sz*dx; a[13]=sz*dy; a[14]=sz*dz;
        wred15(a);
        if (tid == 0) {
            volatile float* gp = g_part[cta];
            #pragma unroll
            for (int q = 0; q < 15; q++) gp[q] = a[q];
            arrive_release(&g_cnt[grp][0]);
        }
    }
    arrived++;

    if (cta != 0) return;

    if (tid < NCNT) {
        const int target = GPC * arrived;
        while (ld_acquire(&g_cnt[tid][0]) < target) { }
    }
    __syncthreads();
    {
        float a[15];
        if (tid < NCTA) {
            volatile float* gp = g_part[tid];
            #pragma unroll
            for (int q = 0; q < 15; q++) a[q] = gp[q];
            wred15(a);
            if ((tid & 31) == 0) {
                #pragma unroll
                for (int q = 0; q < 15; q++) sred[(tid>>5)*15 + q] = a[q];
            }
        }
    }
    __syncthreads();
    if (tid == 0) {
        float R[9], t[3];
        solve_from_sred(sred, R, t);
        out[0]=R[0]; out[1]=R[1]; out[2]=R[2];  out[3]=t[0];
        out[4]=R[3]; out[5]=R[4]; out[6]=R[5];  out[7]=t[1];
        out[8]=R[6]; out[9]=R[7]; out[10]=R[8]; out[11]=t[2];
    }
}

extern "C" void kernel_launch(void* const* d_in, const int* in_sizes, int n_in,
                              void* d_out, int out_size)
{
    const float* p1 = (const float*)d_in[0];
    const float* p2 = (const float*)d_in[1];
    float* out = (float*)d_out;

    int* CNT;
    float* REL;
    cudaGetSymbolAddress((void**)&CNT, g_cnt);
    cudaGetSymbolAddress((void**)&REL, g_rel);
    cudaMemsetAsync(CNT, 0, NCNT*32*sizeof(int), 0);
    cudaMemsetAsync(REL, 0, NCNT*32*sizeof(float), 0);

    static int attr_set = 0;
    if (!attr_set) {
        cudaFuncSetAttribute(icp_all, cudaFuncAttributeMaxDynamicSharedMemorySize,
                             SM_TOTAL);
        attr_set = 1;
    }
    icp_all<<<NCTA, TPB, SM_TOTAL>>>(p1, p2, out);
}

// round 17
// speedup vs baseline: 1.5392x; 1.5392x over previous
#include <cuda_runtime.h>

#define NPTS  4096
#define NCTA  128
#define TPB   512
#define IPC   32          // i-points per CTA
#define NSL   64          // j-slices (strided pairs)
#define STEPS 10
#define NSIT  6           // Newton-Schulz iterations
#define NCNT  8           // arrival counters (16 CTAs each)
#define GPC   (NCTA/NCNT) // 16
#define CONV_THRESH 8     // stop when <= this many matches changed (of 4096)
#define F_APPLYSTOP 64    // flag bit: apply published R, then stop
#define DONEFLAG   128    // stop without applying (matches frozen, R=I)

// shared memory layout (bytes) — SoA p2: qx,qy,qz,qw (16KB each)
#define SM_QX    0
#define SM_QY    (NPTS*4)
#define SM_QZ    (NPTS*8)
#define SM_QW    (NPTS*12)
#define SM_KEY   (NPTS*16)               // u64[NSL][32]  = 16384
#define SM_MYPC  (SM_KEY + NSL*32*8)     // float[96]
#define SM_MYP1  (SM_MYPC + 96*4)        // float[96]
#define SM_SRT   (SM_MYP1 + 96*4)        // float[12] (+pad)
#define SM_SRED  (SM_SRT + 16*4)         // float[4][15] (+pad)
#define SM_PREV  (SM_SRED + 64*4)        // int[32]
#define SM_CHG   (SM_PREV + 32*4)        // int[8]
#define SM_FLG   (SM_CHG + 8*4)          // int[4]
#define SM_TOTAL (SM_FLG + 16 + 64)

// global scratch (no allocations allowed)
__device__ float g_part[NCTA][16];
__device__ float g_RT[12];          // release payload (NOT polled)
__device__ int   g_cnt[NCNT][32];   // word0: arrivals (monotone), word1: changed (monotone)
__device__ int   g_sync[64];        // [48] release flag (own line, write-once per iter)

__device__ __forceinline__ unsigned int fkey(float f) {
    unsigned int u = __float_as_uint(f);
    return (u & 0x80000000u) ? ~u : (u | 0x80000000u);
}

__device__ __forceinline__ void arrive_release(int* ctr) {
    asm volatile("red.release.gpu.global.add.u32 [%0], 1;" :: "l"(ctr) : "memory");
}
__device__ __forceinline__ void addn_relaxed(int* ctr, unsigned n) {
    asm volatile("red.relaxed.gpu.global.add.u32 [%0], %1;" :: "l"(ctr), "r"(n) : "memory");
}
__device__ __forceinline__ int ld_acquire(const int* p) {
    int v;
    asm volatile("ld.acquire.gpu.global.u32 %0, [%1];" : "=r"(v) : "l"(p) : "memory");
    return v;
}
__device__ __forceinline__ void st_release(int* p, int v) {
    asm volatile("st.release.gpu.global.u32 [%0], %1;" :: "l"(p), "r"(v) : "memory");
}

// packed f32x2 helpers (FFMA2 path — per-lane arithmetic identical to fmaf)
__device__ __forceinline__ unsigned long long pack2(float lo, float hi) {
    unsigned long long r;
    asm("mov.b64 %0, {%1, %2};" : "=l"(r) : "f"(lo), "f"(hi));
    return r;
}
__device__ __forceinline__ void unpack2(unsigned long long v, float& lo, float& hi) {
    asm("mov.b64 {%0, %1}, %2;" : "=f"(lo), "=f"(hi) : "l"(v));
}
__device__ __forceinline__ unsigned long long fma2(unsigned long long a,
                                                   unsigned long long b,
                                                   unsigned long long c) {
    unsigned long long d;
    asm("fma.rn.f32x2 %0, %1, %2, %3;" : "=l"(d) : "l"(a), "l"(b), "l"(c));
    return d;
}

// ---------------------------------------------------------------------------
// Newton-Schulz polar: Q = orthogonal polar factor of M (3x3, det(M)>0).
// ---------------------------------------------------------------------------
__device__ __forceinline__ void polar3(const float M[9], float Q[9])
{
    float f2 = 0.f;
    #pragma unroll
    for (int q = 0; q < 9; q++) f2 = fmaf(M[q], M[q], f2);
    float inv = rsqrtf(f2);
    float X[9];
    #pragma unroll
    for (int q = 0; q < 9; q++) X[q] = M[q]*inv;

    #pragma unroll
    for (int it = 0; it < NSIT; it++) {
        float W[9];
        #pragma unroll
        for (int i = 0; i < 3; i++)
            #pragma unroll
            for (int j = 0; j < 3; j++)
                W[3*i+j] = fmaf(X[0+i], X[0+j],
                           fmaf(X[3+i], X[3+j], X[6+i]*X[6+j]));
        float Y[9];
        #pragma unroll
        for (int i = 0; i < 3; i++)
            #pragma unroll
            for (int j = 0; j < 3; j++)
                Y[3*i+j] = fmaf(X[3*i+0], W[0+j],
                           fmaf(X[3*i+1], W[3+j], X[3*i+2]*W[6+j]));
        #pragma unroll
        for (int q = 0; q < 9; q++) X[q] = fmaf(1.5f, X[q], -0.5f*Y[q]);
    }
    #pragma unroll
    for (int q = 0; q < 9; q++) Q[q] = X[q];
}

// warp-reduce 15 accumulators (full warp, fixed order -> deterministic)
__device__ __forceinline__ void wred15(float a[15]) {
    #pragma unroll
    for (int q = 0; q < 15; q++)
        #pragma unroll
        for (int off = 16; off; off >>= 1)
            a[q] += __shfl_down_sync(0xffffffffu, a[q], off);
}

// solve from reduced sums (sred[4][15] in smem) -> R[9], t[3]
__device__ __forceinline__ void solve_from_sred(const float* sred,
                                                float R[9], float t[3])
{
    float s15[15];
    #pragma unroll
    for (int q = 0; q < 15; q++)
        s15[q] = (sred[q] + sred[15+q]) + (sred[30+q] + sred[45+q]);
    const float invN = 1.0f/NPTS;
    float c1[3] = { s15[0]*invN, s15[1]*invN, s15[2]*invN };
    float c2[3] = { s15[3]*invN, s15[4]*invN, s15[5]*invN };
    float M[9];
    #pragma unroll
    for (int i = 0; i < 3; i++)
        #pragma unroll
        for (int j = 0; j < 3; j++)
            M[3*i+j] = s15[6+3*j+i] - (float)NPTS * c1[j] * c2[i];
    polar3(M, R);
    t[0] = c2[0] - (R[0]*c1[0] + R[1]*c1[1] + R[2]*c1[2]);
    t[1] = c2[1] - (R[3]*c1[0] + R[4]*c1[1] + R[5]*c1[2]);
    t[2] = c2[2] - (R[6]*c1[0] + R[7]*c1[1] + R[8]*c1[2]);
}

// ---------------------------------------------------------------------------
// Persistent kernel: R15 structure (best) + thresholded convergence stop.
// Release path: payload on g_RT (not polled), write-once flag on g_sync[48].
// ---------------------------------------------------------------------------
__global__ void __launch_bounds__(TPB, 1)
icp_all(const float* __restrict__ p1, const float* __restrict__ p2,
        float* __restrict__ out)
{
    extern __shared__ unsigned char smem[];
    float*              qxs  = (float*)(smem + SM_QX);
    float*              qys  = (float*)(smem + SM_QY);
    float*              qzs  = (float*)(smem + SM_QZ);
    float*              qws  = (float*)(smem + SM_QW);
    unsigned long long* key  = (unsigned long long*)(smem + SM_KEY);
    float*              mypc = (float*)(smem + SM_MYPC);
    float*              myp1 = (float*)(smem + SM_MYP1);
    float*              srt  = (float*)(smem + SM_SRT);
    float*              sred = (float*)(smem + SM_SRED);
    int*                previdx = (int*)(smem + SM_PREV);
    int*                schg = (int*)(smem + SM_CHG);
    int*                sflg = (int*)(smem + SM_FLG);

    const int cta = blockIdx.x;
    const int tid = threadIdx.x;
    const int grp = cta & (NCNT-1);

    // SoA p2 (+ precomputed 0.5|q|^2); reused all iterations
    for (int j = tid; j < NPTS; j += TPB) {
        float a = p2[j*3+0], b = p2[j*3+1], c = p2[j*3+2];
        qxs[j] = a; qys[j] = b; qzs[j] = c;
        qws[j] = 0.5f*fmaf(a,a,fmaf(b,b,c*c));
    }
    if (tid < IPC) {
        int i = cta*IPC + tid;
        float x = p1[i*3+0], y = p1[i*3+1], z = p1[i*3+2];
        myp1[tid*3+0] = x; myp1[tid*3+1] = y; myp1[tid*3+2] = z;
        mypc[tid*3+0] = x; mypc[tid*3+1] = y; mypc[tid*3+2] = z;
        previdx[tid] = -1;
    }
    __syncthreads();

    const int iblk  = tid & 7;        // 8 i-blocks of 4 points
    const int slice = tid >> 3;       // 64 slices, strided j-pairs
    const int ib4   = iblk*4;

    int arrived = 0;
    int prevChangedTotal = 0;   // CTA0 tid0 only
    int fval = 0;

    for (int k = 0; k < STEPS; k++) {
        // --- NN: 4 i-points, 32 strided j-pairs per thread, FFMA2 packed ---
        {
            float x0=mypc[(ib4+0)*3+0], y0=mypc[(ib4+0)*3+1], z0=mypc[(ib4+0)*3+2];
            float x1=mypc[(ib4+1)*3+0], y1=mypc[(ib4+1)*3+1], z1=mypc[(ib4+1)*3+2];
            float x2=mypc[(ib4+2)*3+0], y2=mypc[(ib4+2)*3+1], z2=mypc[(ib4+2)*3+2];
            float x3=mypc[(ib4+3)*3+0], y3=mypc[(ib4+3)*3+1], z3=mypc[(ib4+3)*3+2];

            const unsigned long long nx0 = pack2(-x0,-x0), ny0 = pack2(-y0,-y0), nz0 = pack2(-z0,-z0);
            const unsigned long long nx1 = pack2(-x1,-x1), ny1 = pack2(-y1,-y1), nz1 = pack2(-z1,-z1);
            const unsigned long long nx2 = pack2(-x2,-x2), ny2 = pack2(-y2,-y2), nz2 = pack2(-z2,-z2);
            const unsigned long long nx3 = pack2(-x3,-x3), ny3 = pack2(-y3,-y3), nz3 = pack2(-z3,-z3);

            float b0=3.4028235e38f, b1=b0, b2=b0, b3=b0;
            int   j0=0, j1=0, j2=0, j3=0;
            int jb = slice*2;                // pairs {jb, jb+1}, stride 128
            #pragma unroll 8
            for (int m = 0; m < 32; m++, jb += 128) {
                unsigned long long QX = *(const unsigned long long*)(qxs + jb);
                unsigned long long QY = *(const unsigned long long*)(qys + jb);
                unsigned long long QZ = *(const unsigned long long*)(qzs + jb);
                unsigned long long QW = *(const unsigned long long*)(qws + jb);
                float sa, sb;
                unpack2(fma2(nx0, QX, fma2(ny0, QY, fma2(nz0, QZ, QW))), sa, sb);
                if (sa < b0) { b0 = sa; j0 = jb; }       // ascending j: first-index ties
                if (sb < b0) { b0 = sb; j0 = jb+1; }
                unpack2(fma2(nx1, QX, fma2(ny1, QY, fma2(nz1, QZ, QW))), sa, sb);
                if (sa < b1) { b1 = sa; j1 = jb; }
                if (sb < b1) { b1 = sb; j1 = jb+1; }
                unpack2(fma2(nx2, QX, fma2(ny2, QY, fma2(nz2, QZ, QW))), sa, sb);
                if (sa < b2) { b2 = sa; j2 = jb; }
                if (sb < b2) { b2 = sb; j2 = jb+1; }
                unpack2(fma2(nx3, QX, fma2(ny3, QY, fma2(nz3, QZ, QW))), sa, sb);
                if (sa < b3) { b3 = sa; j3 = jb; }
                if (sb < b3) { b3 = sb; j3 = jb+1; }
            }
            key[slice*32 + ib4+0] = ((unsigned long long)fkey(b0) << 32) | (unsigned)j0;
            key[slice*32 + ib4+1] = ((unsigned long long)fkey(b1) << 32) | (unsigned)j1;
            key[slice*32 + ib4+2] = ((unsigned long long)fkey(b2) << 32) | (unsigned)j2;
            key[slice*32 + ib4+3] = ((unsigned long long)fkey(b3) << 32) | (unsigned)j3;
        }
        __syncthreads();

        // --- parallel key-reduce: 64 slices -> 8 (256 threads) ---
        if (tid < 256) {
            const int pt  = tid & 31;
            const int oct = tid >> 5;
            unsigned long long best = key[(oct*8)*32 + pt];
            #pragma unroll
            for (int s2 = 1; s2 < 8; s2++) {
                unsigned long long v = key[(oct*8+s2)*32 + pt];
                if (v < best) best = v;
            }
            key[oct*32 + pt] = best;
        }
        __syncthreads();

        // --- warp0: final argmin + changed + partials + arrive ---
        if (tid < 32) {
            unsigned long long best = key[tid];
            #pragma unroll
            for (int s2 = 1; s2 < 8; s2++) {
                unsigned long long v = key[s2*32 + tid];
                if (v < best) best = v;   // (score, j) lexicographic: first-index ties
            }
            const int idx = (int)(unsigned)(best & 0xFFFFFFFFu);
            int changed = (idx != previdx[tid]);
            previdx[tid] = idx;
            unsigned cm = __ballot_sync(0xffffffffu, changed);
            int nch = __popc(cm);

            float dx = qxs[idx], dy = qys[idx], dz = qzs[idx];
            float sx = mypc[tid*3+0], sy = mypc[tid*3+1], sz = mypc[tid*3+2];
            float a[15];
            a[0]=sx; a[1]=sy; a[2]=sz; a[3]=dx; a[4]=dy; a[5]=dz;
            a[6]=sx*dx; a[7]=sx*dy; a[8]=sx*dz;
            a[9]=sy*dx; a[10]=sy*dy; a[11]=sy*dz;
            a[12]=sz*dx; a[13]=sz*dy; a[14]=sz*dz;
            wred15(a);
            if (tid == 0) {
                volatile float* gp = g_part[cta];
                #pragma unroll
                for (int q2 = 0; q2 < 15; q2++) gp[q2] = a[q2];
                if (nch) addn_relaxed(&g_cnt[grp][1], (unsigned)nch);  // exact point count
                arrive_release(&g_cnt[grp][0]);       // orders partials + changed
            }
        }
        arrived++;

        if (cta == 0) {
            if (tid < NCNT) {
                const int target = GPC * arrived;
                while (ld_acquire(&g_cnt[tid][0]) < target) { }
                schg[tid] = *(volatile int*)&g_cnt[tid][1];
            }
            __syncthreads();
            {
                float a[15];
                if (tid < NCTA) {
                    volatile float* gp = g_part[tid];
                    #pragma unroll
                    for (int q = 0; q < 15; q++) a[q] = gp[q];
                    wred15(a);
                    if ((tid & 31) == 0) {
                        #pragma unroll
                        for (int q = 0; q < 15; q++) sred[(tid>>5)*15 + q] = a[q];
                    }
                }
            }
            __syncthreads();
            if (tid == 0) {
                int total = ((schg[0]+schg[1])+(schg[2]+schg[3]))
                          + ((schg[4]+schg[5])+(schg[6]+schg[7]));
                int newly = total - prevChangedTotal;
                prevChangedTotal = total;
                int f;
                if (newly == 0) {
                    f = (k+1) | DONEFLAG;     // frozen matches: R=I, stop (no apply)
                } else {
                    float R[9], t[3];
                    solve_from_sred(sred, R, t);
                    #pragma unroll
                    for (int q = 0; q < 9; q++) srt[q] = R[q];
                    srt[9]=t[0]; srt[10]=t[1]; srt[11]=t[2];
                    volatile float* grt = g_RT;          // payload line (not polled)
                    #pragma unroll
                    for (int q = 0; q < 9; q++) grt[q] = R[q];
                    grt[9]=t[0]; grt[10]=t[1]; grt[11]=t[2];
                    f = (k+1) | ((newly <= CONV_THRESH) ? F_APPLYSTOP : 0);
                }
                st_release(&g_sync[48], f);   // single write-once flag (own line)
                sflg[0] = f;
            }
            __syncthreads();
            fval = sflg[0];
        } else {
            // workers: poll flag (quiescent line), then read payload line
            if (tid < 12) {
                int f;
                while (((f = ld_acquire(&g_sync[48])) & 63) < k + 1) { }
                if (tid == 0) sflg[0] = f;
                srt[tid] = ((volatile float*)g_RT)[tid];   // stale-safe if DONEFLAG
            }
            __syncthreads();
            fval = sflg[0];
        }

        // --- apply R_k, t_k (unless DONE-without-apply) ---
        if (!(fval & DONEFLAG) && tid < IPC) {
            float x = mypc[tid*3+0], y = mypc[tid*3+1], z = mypc[tid*3+2];
            float nx = fmaf(srt[0],x, fmaf(srt[1],y, fmaf(srt[2],z, srt[9])));
            float ny = fmaf(srt[3],x, fmaf(srt[4],y, fmaf(srt[5],z, srt[10])));
            float nz = fmaf(srt[6],x, fmaf(srt[7],y, fmaf(srt[8],z, srt[11])));
            mypc[tid*3+0] = nx; mypc[tid*3+1] = ny; mypc[tid*3+2] = nz;
        }
        __syncthreads();
        if (fval & (DONEFLAG | F_APPLYSTOP)) break;
    }

    // --- final solve: Kabsch(p1 -> pc_final) ---
    if (tid < 32) {
        float sx = myp1[tid*3+0], sy = myp1[tid*3+1], sz = myp1[tid*3+2];
        float dx = mypc[tid*3+0], dy = mypc[tid*3+1], dz = mypc[tid*3+2];
        float a[15];
        a[0]=sx; a[1]=sy; a[2]=sz; a[3]=dx; a[4]=dy; a[5]=dz;
        a[6]=sx*dx; a[7]=sx*dy; a[8]=sx*dz;
        a[9]=sy*dx; a[10]=sy*dy; a[11]=sy*dz;
        a[12]=sz*dx; a[13]=sz*dy; a[14]=sz*dz;
        wred15(a);
        if (tid == 0) {
            volatile float* gp = g_part[cta];
            #pragma unroll
            for (int q = 0; q < 15; q++) gp[q] = a[q];
            arrive_release(&g_cnt[grp][0]);
        }
    }
    arrived++;

    if (cta != 0) return;

    if (tid < NCNT) {
        const int target = GPC * arrived;
        while (ld_acquire(&g_cnt[tid][0]) < target) { }
    }
    __syncthreads();
    {
        float a[15];
        if (tid < NCTA) {
            volatile float* gp = g_part[tid];
            #pragma unroll
            for (int q = 0; q < 15; q++) a[q] = gp[q];
            wred15(a);
            if ((tid & 31) == 0) {
                #pragma unroll
                for (int q = 0; q < 15; q++) sred[(tid>>5)*15 + q] = a[q];
            }
        }
    }
    __syncthreads();
    if (tid == 0) {
        float R[9], t[3];
        solve_from_sred(sred, R, t);
        out[0]=R[0]; out[1]=R[1]; out[2]=R[2];  out[3]=t[0];
        out[4]=R[3]; out[5]=R[4]; out[6]=R[5];  out[7]=t[1];
        out[8]=R[6]; out[9]=R[7]; out[10]=R[8]; out[11]=t[2];
    }
}

extern "C" void kernel_launch(void* const* d_in, const int* in_sizes, int n_in,
                              void* d_out, int out_size)
{
    const float* p1 = (const float*)d_in[0];
    const float* p2 = (const float*)d_in[1];
    float* out = (float*)d_out;

    int *SYNC, *CNT;
    cudaGetSymbolAddress((void**)&SYNC, g_sync);
    cudaGetSymbolAddress((void**)&CNT,  g_cnt);
    cudaMemsetAsync(SYNC, 0, 64*sizeof(int), 0);
    cudaMemsetAsync(CNT,  0, NCNT*32*sizeof(int), 0);

    static int attr_set = 0;
    if (!attr_set) {
        cudaFuncSetAttribute(icp_all, cudaFuncAttributeMaxDynamicSharedMemorySize,
                             SM_TOTAL);
        attr_set = 1;
    }
    icp_all<<<NCTA, TPB, SM_TOTAL>>>(p1, p2, out);
}